// round 5
// baseline (speedup 1.0000x reference)
#include <cuda_runtime.h>
#include <cuda_bf16.h>
#include <cstdint>

// Problem constants (SheafGluingPoly: B=4, M=50000, D=8, E=1600000, POLY_K=3, LAM=1)
#define B_CONST 4
#define D_CONST 8
#define MAX_MBD 1600000   // B*M*D
#define MAX_E   1600000

// Scratch: ping-pong vertex state in transposed [m][b][d] layout (128B/vertex),
// plus packed (src,dst) pairs.
__device__ float g_bufA[MAX_MBD];
__device__ float g_bufB[MAX_MBD];
__device__ int2  g_pair[MAX_E];

// ---------------------------------------------------------------------------
// init (fused with pair packing):
//   v(A) = transpose(c0), out = pc[0]*c0, acc(B) = 0, pair[e] = (src,dst)
// ---------------------------------------------------------------------------
__global__ void init_kernel(const float* __restrict__ c0,
                            const int*   __restrict__ src,
                            const int*   __restrict__ dst,
                            const float* __restrict__ pc,
                            float* __restrict__ out,
                            float* __restrict__ v,
                            float* __restrict__ accz,
                            int2*  __restrict__ pair,
                            int M, int E)
{
    int i = blockIdx.x * blockDim.x + threadIdx.x;
    int n = M * 32;
    if (i < n) {
        int m = i >> 5;
        int t = i & 31;
        int b = t >> 3;
        int d = t & 7;
        int src_idx = (b * M + m) * 8 + d;   // [b][m][d] layout of c0 / out
        float val = c0[src_idx];
        v[i] = val;
        out[src_idx] = pc[0] * val;
        accz[i] = 0.0f;
    }
    if (i < E) {
        pair[i] = make_int2(src[i], dst[i]);
    }
}

// ---------------------------------------------------------------------------
// edge kernel: one warp per edge. lane t = b*8 + d (d = d2 d1 d0).
// Register k = (k2, k01) holds column d of row rho(k,d) = ((k01 ^ d01) | k2*4):
//   addr = base + rho*32 + d*4 ; for fixed k, bit7 (=k2) is constant across
//   lanes -> every LDG touches exactly ONE 128B line.
// Math:
//   z[k] = S[k]*ps - D[k]*pd          (partial of r[rho(k,d)] at column d)
//   keep-low butterfly (stages 1,2 exchange k^1,k^2; stage 4 is identity on
//   rho, so plain self-shfl):  R0 = r[d01], R1 = r[d01+4]  (full sums)
//   allgather: r[(x^d01)|k2*4] = shfl_xor(Rk2, x)
//   cs[d] = sum_k S[k]*r[rho(k,d)],  cd[d] = sum_k D[k]*r[rho(k,d)]
//   acc[src][b][d] += cs ;  acc[dst][b][d] += -cd
// ---------------------------------------------------------------------------
__global__ void __launch_bounds__(256)
edge_kernel(const float* __restrict__ v,
            const int2*  __restrict__ pair,
            const float* __restrict__ Rsrc,
            const float* __restrict__ Rdst,
            float*       __restrict__ acc,
            int E)
{
    int e = (blockIdx.x * blockDim.x + threadIdx.x) >> 5;
    if (e >= E) return;
    int t = threadIdx.x & 31;
    int d = t & 7;

    int2 pr = __ldg(pair + e);

    const char* SB = (const char*)Rsrc + (size_t)e * 256;
    const char* DB = (const char*)Rdst + (size_t)e * 256;

    // o0 = d*4 + (d&3)*32 ; bits5-6 of o0 are d01, so XOR with x*32 gives
    // row (x ^ d01) with no carries.
    unsigned o0 = (unsigned)(d * 4 + (d & 3) * 32);

    float S[8], D[8];
#pragma unroll
    for (int x = 0; x < 4; x++) {
        unsigned ox = o0 ^ (unsigned)(x << 5);
        const float* pS = (const float*)(SB + ox);
        const float* pD = (const float*)(DB + ox);
        S[x]     = __ldg(pS);        // row (x^d01)     , col d
        S[x + 4] = __ldg(pS + 32);   // row (x^d01) + 4 , col d  (imm +128B)
        D[x]     = __ldg(pD);
        D[x + 4] = __ldg(pD + 32);
    }

    float ps = __ldg(v + pr.x * 32 + t);
    float pd = __ldg(v + pr.y * 32 + t);

    // z[k] = S[k]*ps - D[k]*pd
    float z[8];
#pragma unroll
    for (int k = 0; k < 8; k++) {
        z[k] = fmaf(S[k], ps, -(D[k] * pd));
    }

    const unsigned FULL = 0xffffffffu;

    // keep-low butterfly, SEL-free
    z[0] += __shfl_xor_sync(FULL, z[1], 1);
    z[2] += __shfl_xor_sync(FULL, z[3], 1);
    z[4] += __shfl_xor_sync(FULL, z[5], 1);
    z[6] += __shfl_xor_sync(FULL, z[7], 1);
    z[0] += __shfl_xor_sync(FULL, z[2], 2);
    z[4] += __shfl_xor_sync(FULL, z[6], 2);
    float R0 = z[0] + __shfl_xor_sync(FULL, z[0], 4);  // r[d01]
    float R1 = z[4] + __shfl_xor_sync(FULL, z[4], 4);  // r[d01 + 4]

    // allgather + transpose FMAs
    float cs = S[0] * R0;
    float cd = D[0] * R0;
    cs = fmaf(S[4], R1, cs);
    cd = fmaf(D[4], R1, cd);
#pragma unroll
    for (int x = 1; x < 4; x++) {
        float r0x = __shfl_xor_sync(FULL, R0, x);  // r[x^d01]
        float r1x = __shfl_xor_sync(FULL, R1, x);  // r[(x^d01)+4]
        cs = fmaf(S[x],     r0x, cs);
        cd = fmaf(D[x],     r0x, cd);
        cs = fmaf(S[x + 4], r1x, cs);
        cd = fmaf(D[x + 4], r1x, cd);
    }

    atomicAdd(acc + pr.x * 32 + t, cs);
    atomicAdd(acc + pr.y * 32 + t, -cd);
}

// ---------------------------------------------------------------------------
// update: out[b][m][d] += pc[k] * acc[m][b][d]; optionally zero the other buffer
// ---------------------------------------------------------------------------
__global__ void update_kernel(const float* __restrict__ acc,
                              const float* __restrict__ pc,
                              int k,
                              float* __restrict__ out,
                              float* __restrict__ zother,
                              int M)
{
    int i = blockIdx.x * blockDim.x + threadIdx.x;
    int n = M * 32;
    if (i >= n) return;
    int m = i >> 5;
    int t = i & 31;
    int b = t >> 3;
    int d = t & 7;
    float val = acc[i];
    int oi = (b * M + m) * 8 + d;
    out[oi] += pc[k] * val;
    if (zother) zother[i] = 0.0f;
}

// ---------------------------------------------------------------------------
// launch  (7 launches total; ncu -s 5 captures launch #6 = 3rd edge_kernel)
// ---------------------------------------------------------------------------
extern "C" void kernel_launch(void* const* d_in, const int* in_sizes, int n_in,
                              void* d_out, int out_size)
{
    const float* c0  = (const float*)d_in[0];
    const int*   src = (const int*)  d_in[1];
    const int*   dst = (const int*)  d_in[2];
    const float* Rs  = (const float*)d_in[3];
    const float* Rd  = (const float*)d_in[4];
    const float* pc  = (const float*)d_in[5];
    float* out = (float*)d_out;

    int E = in_sizes[1];
    int M = in_sizes[0] / (B_CONST * D_CONST);

    float* bufA;  float* bufB;  int2* pairp;
    cudaGetSymbolAddress((void**)&bufA,  g_bufA);
    cudaGetSymbolAddress((void**)&bufB,  g_bufB);
    cudaGetSymbolAddress((void**)&pairp, g_pair);

    int nV = M * 32;
    int tb = 256;
    int nInit = (nV > E) ? nV : E;
    int gI = (nInit + tb - 1) / tb;
    int gV = (nV + tb - 1) / tb;
    int gE = (E * 32 + tb - 1) / tb;

    init_kernel<<<gI, tb>>>(c0, src, dst, pc, out, bufA, bufB, pairp, M, E);

    // k = 1: B <- L(A); out += pc[1]*B; zero A
    edge_kernel<<<gE, tb>>>(bufA, pairp, Rs, Rd, bufB, E);
    update_kernel<<<gV, tb>>>(bufB, pc, 1, out, bufA, M);

    // k = 2: A <- L(B); out += pc[2]*A; zero B
    edge_kernel<<<gE, tb>>>(bufB, pairp, Rs, Rd, bufA, E);
    update_kernel<<<gV, tb>>>(bufA, pc, 2, out, bufB, M);

    // k = 3: B <- L(A); out += pc[3]*B
    edge_kernel<<<gE, tb>>>(bufA, pairp, Rs, Rd, bufB, E);
    update_kernel<<<gV, tb>>>(bufB, pc, 3, out, nullptr, M);
}